// round 4
// baseline (speedup 1.0000x reference)
#include <cuda_runtime.h>

#define D16 16
#define H64 64
#define NMASK 32767
#define EPSQ 1e-10f
#define L2E 1.4426950408889634f

#define TPB 64
#define IPT 8
#define BLK_PER_PAIR 64   // 64 blocks * 64 threads * 8 items = 32768 >= 32767
#define NPAIR 16

__device__ float    g_part[NPAIR * BLK_PER_PAIR];
__device__ unsigned g_cnt[NPAIR];   // zero-initialized; reset by last block each run

static __device__ __forceinline__ unsigned long long pk2(float lo, float hi) {
    unsigned long long r;
    asm("mov.b64 %0, {%1, %2};" : "=l"(r) : "f"(lo), "f"(hi));
    return r;
}
static __device__ __forceinline__ void upk2(unsigned long long v, float& lo, float& hi) {
    asm("mov.b64 {%0, %1}, %2;" : "=f"(lo), "=f"(hi) : "l"(v));
}
static __device__ __forceinline__ unsigned long long ffma2(unsigned long long a,
                                                           unsigned long long b,
                                                           unsigned long long c) {
    unsigned long long d;
    asm("fma.rn.f32x2 %0, %1, %2, %3;" : "=l"(d) : "l"(a), "l"(b), "l"(c));
    return d;
}
static __device__ __forceinline__ float ex2f(float x) {
    float y; asm("ex2.approx.f32 %0, %1;" : "=f"(y) : "f"(x)); return y;
}
static __device__ __forceinline__ float lg2a(float x) {
    float y; asm("lg2.approx.f32 %0, %1;" : "=f"(y) : "f"(x)); return y;
}
static __device__ __forceinline__ float rcpf(float x) {
    float y; asm("rcp.approx.f32 %0, %1;" : "=f"(y) : "f"(x)); return y;
}

__global__ void __launch_bounds__(TPB, 6)
phi_kernel(const float* __restrict__ state,
           const float* __restrict__ cw1, const float* __restrict__ cb1,
           const float* __restrict__ cw2, const float* __restrict__ cb2,
           const float* __restrict__ ew1, const float* __restrict__ eb1,
           const float* __restrict__ ew2, const float* __restrict__ eb2,
           float* __restrict__ out) {
    __shared__ float acc_sm[H64 * TPB];              // per-thread Gray accumulator
    __shared__ float c_sm[H64 * D16];                // [h][d] = W1[h,d]*state[b,d] (init path)
    __shared__ float cT_sm[D16 * H64];               // [d][h] transpose (inner loop, float4 reads)
    __shared__ unsigned long long w2p_sm[H64 * D16]; // [h][j] = pack(W2[j,h], W2[j,h])
    __shared__ float T_sm[H64];                      // 2*b1 + sum_d c[h][d]
    __shared__ float b1_sm[H64];
    __shared__ float b2L_sm[D16];                    // b2[j] * log2(e)
    __shared__ float p_sm[D16];
    __shared__ float C_sm;
    __shared__ float hfull_sm[H64];
    __shared__ float wmin_sm[TPB / 32];
    __shared__ int   last_sm;

    const int pair = blockIdx.x / BLK_PER_PAIR;
    const int cblk = blockIdx.x % BLK_PER_PAIR;
    const int b    = pair & 7;
    const int dir  = pair >> 3;
    const float* __restrict__ w1 = dir ? ew1 : cw1;
    const float* __restrict__ b1 = dir ? eb1 : cb1;
    const float* __restrict__ w2 = dir ? ew2 : cw2;
    const float* __restrict__ b2 = dir ? eb2 : cb2;

    const int tid = threadIdx.x;

    // ---- stage shared tables ----
    for (int idx = tid; idx < H64 * D16; idx += TPB) {
        int h = idx >> 4, d = idx & 15;
        float cv = w1[h * D16 + d] * state[b * D16 + d];
        c_sm[idx] = cv;
        cT_sm[d * H64 + h] = cv;
        float wv = w2[d * H64 + h];   // d plays the role of output index j: W2[j, h]
        w2p_sm[idx] = pk2(wv, wv);
    }
    if (tid < D16) b2L_sm[tid] = b2[tid] * L2E;
    for (int h = tid; h < H64; h += TPB) b1_sm[h] = b1[h];
    __syncthreads();

    if (tid < H64) {
        float s = 0.f;
        #pragma unroll
        for (int d = 0; d < D16; ++d) s += c_sm[tid * D16 + d];
        float t = 2.f * b1_sm[tid] + s;
        T_sm[tid] = t;
        hfull_sm[tid] = fmaxf(t - b1_sm[tid], 0.f);  // full (unmasked) hidden
    }
    __syncthreads();
    // ---- full-state softmax p, C = sum p*log2(p); warp-cooperative ----
    if (tid < 32) {
        float e = 0.f;
        const int j = tid & 15;
        if (tid < D16) {
            float z = b2[j];
            #pragma unroll
            for (int h = 0; h < H64; ++h) z = fmaf(w2[j * H64 + h], hfull_sm[h], z);
            e = ex2f(z * L2E);
        }
        float S = e;
        #pragma unroll
        for (int off = 8; off; off >>= 1) S += __shfl_xor_sync(0xffffffffu, S, off);
        if (tid < D16) {
            float p = fmaxf(e * rcpf(S), EPSQ);
            p_sm[j] = p;
            float cpart = p * lg2a(p);
            #pragma unroll
            for (int off = 8; off; off >>= 1)
                cpart += __shfl_xor_sync(0x0000ffffu, cpart, off);
            if (tid == 0) C_sm = cpart;
        }
    }
    __syncthreads();

    const float Cc = C_sm;
    const int t  = cblk * TPB + tid;
    const int i0 = 1 + t * IPT;
    float locmin = __int_as_float(0x7f800000);  // +inf

    if (i0 <= NMASK) {
        const int i1 = min(i0 + IPT, NMASK + 1);
        unsigned m = (unsigned)i0 ^ ((unsigned)i0 >> 1);  // 15-bit Gray code

        // ---- init accumulator in shared: acc = b1 + sum_{d in m} c_d ----
        #pragma unroll
        for (int h = 0; h < H64; ++h) {
            float a = b1_sm[h];
            #pragma unroll
            for (int d = 0; d < D16; ++d) {
                float bd = ((m >> d) & 1u) ? 1.f : 0.f;
                a = fmaf(bd, c_sm[h * D16 + d], a);
            }
            acc_sm[h * TPB + tid] = a;
        }

        float s = 0.f;
        int dd = 0;
        for (int i = i0; i < i1; ++i) {
            if (i != i0) {
                dd = __ffs(i) - 1;          // Gray transition bit
                m ^= (1u << dd);
                s = ((m >> dd) & 1u) ? 1.f : -1.f;
            }

            unsigned long long o2[D16];
            #pragma unroll
            for (int j = 0; j < D16; ++j) o2[j] = 0ull;

            // ---- fused Gray update + dual second layer (packed f32x2) ----
            #pragma unroll
            for (int hb = 0; hb < H64 / 4; ++hb) {
                const float4 Tv = reinterpret_cast<const float4*>(T_sm)[hb];
                const float4 Cv = reinterpret_cast<const float4*>(&cT_sm[dd * H64])[hb];
                #pragma unroll
                for (int k = 0; k < 4; ++k) {
                    const int h = hb * 4 + k;
                    float cv = (k == 0) ? Cv.x : (k == 1) ? Cv.y : (k == 2) ? Cv.z : Cv.w;
                    float a = fmaf(s, cv, acc_sm[h * TPB + tid]);  // s=0 first iter: no-op
                    acc_sm[h * TPB + tid] = a;
                    float tt = (k == 0) ? Tv.x : (k == 1) ? Tv.y : (k == 2) ? Tv.z : Tv.w;
                    float ra = fmaxf(a, 0.f);
                    float rb = fmaxf(tt - a, 0.f);
                    unsigned long long rab = pk2(ra, rb);
                    const ulonglong2* wrow = reinterpret_cast<const ulonglong2*>(&w2p_sm[h * D16]);
                    #pragma unroll
                    for (int jj = 0; jj < 8; ++jj) {
                        ulonglong2 wv = wrow[jj];
                        o2[2 * jj]     = ffma2(rab, wv.x, o2[2 * jj]);
                        o2[2 * jj + 1] = ffma2(rab, wv.y, o2[2 * jj + 1]);
                    }
                }
            }

            // ---- dual softmax (exponentials overwrite o2 in place) ----
            float Sa = 0.f, Sb = 0.f;
            #pragma unroll
            for (int j = 0; j < D16; ++j) {
                float za, zb;
                upk2(o2[j], za, zb);
                float bl = b2L_sm[j];
                float e1 = ex2f(fmaf(za, L2E, bl));
                float e2 = ex2f(fmaf(zb, L2E, bl));
                o2[j] = pk2(e1, e2);
                Sa += e1; Sb += e2;
            }
            float ha  = 0.5f * rcpf(Sa);
            float hb2 = 0.5f * rcpf(Sb);
            float klq = 0.f;
            #pragma unroll
            for (int j = 0; j < D16; ++j) {
                float e1, e2;
                upk2(o2[j], e1, e2);
                float q = fmaf(e1, ha, e2 * hb2);
                q = fmaxf(q, EPSQ);
                klq = fmaf(p_sm[j], lg2a(q), klq);
            }
            locmin = fminf(locmin, Cc - klq);
        }
    }

    // ---- block min-reduce ----
    #pragma unroll
    for (int off = 16; off; off >>= 1)
        locmin = fminf(locmin, __shfl_xor_sync(0xffffffffu, locmin, off));
    if ((tid & 31) == 0) wmin_sm[tid >> 5] = locmin;
    __syncthreads();

    // ---- last-block-done global reduce (single kernel, replay-safe) ----
    if (tid == 0) {
        float v = fminf(wmin_sm[0], wmin_sm[1]);
        g_part[pair * BLK_PER_PAIR + cblk] = v;
        __threadfence();
        unsigned r = atomicAdd(&g_cnt[pair], 1u);
        last_sm = (r == BLK_PER_PAIR - 1);
    }
    __syncthreads();
    if (last_sm) {
        if (tid < 32) {
            __threadfence();
            const volatile float* vp = g_part + pair * BLK_PER_PAIR;
            float v = fminf(vp[tid], vp[tid + 32]);
            #pragma unroll
            for (int off = 16; off; off >>= 1)
                v = fminf(v, __shfl_xor_sync(0xffffffffu, v, off));
            if (tid == 0) {
                out[pair] = v;          // out layout: [dir*8 + b] == pair
                g_cnt[pair] = 0;        // reset for next replay (deterministic)
            }
        }
    }
}

extern "C" void kernel_launch(void* const* d_in, const int* in_sizes, int n_in,
                              void* d_out, int out_size) {
    const float* state = (const float*)d_in[0];
    const float* cw1 = (const float*)d_in[1];
    const float* cb1 = (const float*)d_in[2];
    const float* cw2 = (const float*)d_in[3];
    const float* cb2 = (const float*)d_in[4];
    const float* ew1 = (const float*)d_in[5];
    const float* eb1 = (const float*)d_in[6];
    const float* ew2 = (const float*)d_in[7];
    const float* eb2 = (const float*)d_in[8];
    float* out = (float*)d_out;

    phi_kernel<<<NPAIR * BLK_PER_PAIR, TPB>>>(state, cw1, cb1, cw2, cb2,
                                              ew1, eb1, ew2, eb2, out);
}

// round 6
// speedup vs baseline: 1.5611x; 1.5611x over previous
#include <cuda_runtime.h>

#define D16 16
#define H64 64
#define NMASK 32767
#define EPSQ 1e-10f
#define L2E 1.4426950408889634f

#define TPB 64
#define IPT 16            // masks per thread (processed as 8 Gray-adjacent pairs)
#define BLK_PER_PAIR 32   // 32 blocks * 64 threads * 16 masks = 32768 >= 32767
#define NPAIR 16

__device__ float    g_part[NPAIR * BLK_PER_PAIR];
__device__ unsigned g_cnt[NPAIR];   // zero-initialized; reset by last block each run

static __device__ __forceinline__ unsigned long long pk2(float lo, float hi) {
    unsigned long long r;
    asm("mov.b64 %0, {%1, %2};" : "=l"(r) : "f"(lo), "f"(hi));
    return r;
}
static __device__ __forceinline__ void upk2(unsigned long long v, float& lo, float& hi) {
    asm("mov.b64 {%0, %1}, %2;" : "=f"(lo), "=f"(hi) : "l"(v));
}
static __device__ __forceinline__ unsigned long long ffma2(unsigned long long a,
                                                           unsigned long long b,
                                                           unsigned long long c) {
    unsigned long long d;
    asm("fma.rn.f32x2 %0, %1, %2, %3;" : "=l"(d) : "l"(a), "l"(b), "l"(c));
    return d;
}
static __device__ __forceinline__ float ex2f(float x) {
    float y; asm("ex2.approx.f32 %0, %1;" : "=f"(y) : "f"(x)); return y;
}
static __device__ __forceinline__ float lg2a(float x) {
    float y; asm("lg2.approx.f32 %0, %1;" : "=f"(y) : "f"(x)); return y;
}
static __device__ __forceinline__ float rcpf(float x) {
    float y; asm("rcp.approx.f32 %0, %1;" : "=f"(y) : "f"(x)); return y;
}

__global__ void __launch_bounds__(TPB, 5)
phi_kernel(const float* __restrict__ state,
           const float* __restrict__ cw1, const float* __restrict__ cb1,
           const float* __restrict__ cw2, const float* __restrict__ cb2,
           const float* __restrict__ ew1, const float* __restrict__ eb1,
           const float* __restrict__ ew2, const float* __restrict__ eb2,
           float* __restrict__ out) {
    __shared__ float acc_sm[H64 * TPB];              // per-thread Gray accumulator
    __shared__ float c_sm[H64 * D16];                // [h][d] = W1[h,d]*state[b,d] (init path)
    __shared__ float cT_sm[D16 * H64];               // [d][h] transpose (inner loop, float4 reads)
    __shared__ unsigned long long w2p_sm[H64 * D16]; // [h][j] = pack(W2[j,h], W2[j,h])
    __shared__ float T_sm[H64];                      // 2*b1 + sum_d c[h][d]
    __shared__ float b1_sm[H64];
    __shared__ float b2L_sm[D16];                    // b2[j] * log2(e)
    __shared__ float p_sm[D16];
    __shared__ float C_sm;
    __shared__ float hfull_sm[H64];
    __shared__ float wmin_sm[TPB / 32];
    __shared__ int   last_sm;

    const int pair = blockIdx.x / BLK_PER_PAIR;
    const int cblk = blockIdx.x % BLK_PER_PAIR;
    const int b    = pair & 7;
    const int dir  = pair >> 3;
    const float* __restrict__ w1 = dir ? ew1 : cw1;
    const float* __restrict__ b1 = dir ? eb1 : cb1;
    const float* __restrict__ w2 = dir ? ew2 : cw2;
    const float* __restrict__ b2 = dir ? eb2 : cb2;

    const int tid = threadIdx.x;

    // ---- stage shared tables ----
    for (int idx = tid; idx < H64 * D16; idx += TPB) {
        int h = idx >> 4, d = idx & 15;
        float cv = w1[h * D16 + d] * state[b * D16 + d];
        c_sm[idx] = cv;
        cT_sm[d * H64 + h] = cv;
        float wv = w2[d * H64 + h];   // d plays the role of output index j: W2[j, h]
        w2p_sm[idx] = pk2(wv, wv);
    }
    if (tid < D16) b2L_sm[tid] = b2[tid] * L2E;
    {
        b1_sm[tid] = b1[tid];
        if (tid + TPB < H64) b1_sm[tid + TPB] = b1[tid + TPB];
    }
    __syncthreads();

    {   // T and full hidden (one h per thread covers 0..63 since TPB=64)
        float s = 0.f;
        #pragma unroll
        for (int d = 0; d < D16; ++d) s += c_sm[tid * D16 + d];
        float t = 2.f * b1_sm[tid] + s;
        T_sm[tid] = t;
        hfull_sm[tid] = fmaxf(t - b1_sm[tid], 0.f);
    }
    __syncthreads();
    // ---- full-state softmax p, C = sum p*log2(p); warp-cooperative ----
    if (tid < 32) {
        float e = 0.f;
        const int j = tid & 15;
        if (tid < D16) {
            float z = b2[j];
            #pragma unroll
            for (int h = 0; h < H64; ++h) z = fmaf(w2[j * H64 + h], hfull_sm[h], z);
            e = ex2f(z * L2E);
        }
        float S = e;
        #pragma unroll
        for (int off = 8; off; off >>= 1) S += __shfl_xor_sync(0xffffffffu, S, off);
        if (tid < D16) {
            float p = fmaxf(e * rcpf(S), EPSQ);
            p_sm[j] = p;
            float cpart = p * lg2a(p);
            #pragma unroll
            for (int off = 8; off; off >>= 1)
                cpart += __shfl_xor_sync(0x0000ffffu, cpart, off);
            if (tid == 0) C_sm = cpart;
        }
    }
    __syncthreads();

    const float Cc = C_sm;
    const int t  = cblk * TPB + tid;
    const int i0 = 1 + t * IPT;
    float locmin = __int_as_float(0x7f800000);  // +inf

    if (i0 <= NMASK) {
        const int i1 = min(i0 + IPT, NMASK + 1);
        unsigned m = (unsigned)i0 ^ ((unsigned)i0 >> 1);  // gray(i0), i0 odd

        // ---- init accumulator in shared: acc = b1 + sum_{d in m} c_d ----
        #pragma unroll
        for (int h = 0; h < H64; ++h) {
            float a = b1_sm[h];
            #pragma unroll
            for (int d = 0; d < D16; ++d) {
                float bd = ((m >> d) & 1u) ? 1.f : 0.f;
                a = fmaf(bd, c_sm[h * D16 + d], a);
            }
            acc_sm[h * TPB + tid] = a;
        }

        // ---- pair loop: masks (i, i+1), i odd ----
        for (int i = i0; i < i1; i += 2) {
            const bool first = (i == i0);
            const bool has2  = (i + 1 < i1);

            float s1;
            if (first) { s1 = 0.f; }
            else       { m ^= 1u; s1 = (m & 1u) ? 1.f : -1.f; }  // odd i: bit 0 flips

            int dd2 = __ffs(i + 1) - 1;          // transition i -> i+1
            float s2 = 0.f;
            if (has2) {
                m ^= (1u << dd2);
                s2 = ((m >> dd2) & 1u) ? 1.f : -1.f;
            }

            unsigned long long o2x[D16], o2y[D16];
            #pragma unroll
            for (int j = 0; j < D16; ++j) { o2x[j] = 0ull; o2y[j] = 0ull; }

            // ---- fused dual Gray update + two dual second layers (packed f32x2) ----
            #pragma unroll
            for (int hb = 0; hb < H64 / 4; ++hb) {
                const float4 Tv  = reinterpret_cast<const float4*>(T_sm)[hb];
                const float4 Cv0 = reinterpret_cast<const float4*>(&cT_sm[0])[hb];
                const float4 Cv2 = reinterpret_cast<const float4*>(&cT_sm[dd2 * H64])[hb];
                #pragma unroll
                for (int k = 0; k < 4; ++k) {
                    const int h = hb * 4 + k;
                    float cv0 = (k == 0) ? Cv0.x : (k == 1) ? Cv0.y : (k == 2) ? Cv0.z : Cv0.w;
                    float cv2 = (k == 0) ? Cv2.x : (k == 1) ? Cv2.y : (k == 2) ? Cv2.z : Cv2.w;
                    float tt  = (k == 0) ? Tv.x  : (k == 1) ? Tv.y  : (k == 2) ? Tv.z  : Tv.w;
                    float a0 = acc_sm[h * TPB + tid];
                    float a1 = fmaf(s1, cv0, a0);
                    float a2 = fmaf(s2, cv2, a1);
                    acc_sm[h * TPB + tid] = a2;
                    unsigned long long rab1 = pk2(fmaxf(a1, 0.f), fmaxf(tt - a1, 0.f));
                    unsigned long long rab2 = pk2(fmaxf(a2, 0.f), fmaxf(tt - a2, 0.f));
                    const ulonglong2* wrow = reinterpret_cast<const ulonglong2*>(&w2p_sm[h * D16]);
                    #pragma unroll
                    for (int jj = 0; jj < 8; ++jj) {
                        ulonglong2 wv = wrow[jj];
                        o2x[2 * jj]     = ffma2(rab1, wv.x, o2x[2 * jj]);
                        o2x[2 * jj + 1] = ffma2(rab1, wv.y, o2x[2 * jj + 1]);
                        o2y[2 * jj]     = ffma2(rab2, wv.x, o2y[2 * jj]);
                        o2y[2 * jj + 1] = ffma2(rab2, wv.y, o2y[2 * jj + 1]);
                    }
                }
            }

            // ---- dual softmax + KL, mask 1 ----
            {
                float Sa = 0.f, Sb = 0.f;
                #pragma unroll
                for (int j = 0; j < D16; ++j) {
                    float za, zb;
                    upk2(o2x[j], za, zb);
                    float bl = b2L_sm[j];
                    float e1 = ex2f(fmaf(za, L2E, bl));
                    float e2 = ex2f(fmaf(zb, L2E, bl));
                    o2x[j] = pk2(e1, e2);
                    Sa += e1; Sb += e2;
                }
                float ha  = 0.5f * rcpf(Sa);
                float hb2 = 0.5f * rcpf(Sb);
                float klq = 0.f;
                #pragma unroll
                for (int j = 0; j < D16; ++j) {
                    float e1, e2;
                    upk2(o2x[j], e1, e2);
                    float q = fmaxf(fmaf(e1, ha, e2 * hb2), EPSQ);
                    klq = fmaf(p_sm[j], lg2a(q), klq);
                }
                locmin = fminf(locmin, Cc - klq);
            }
            // ---- dual softmax + KL, mask 2 (guarded) ----
            {
                float Sa = 0.f, Sb = 0.f;
                #pragma unroll
                for (int j = 0; j < D16; ++j) {
                    float za, zb;
                    upk2(o2y[j], za, zb);
                    float bl = b2L_sm[j];
                    float e1 = ex2f(fmaf(za, L2E, bl));
                    float e2 = ex2f(fmaf(zb, L2E, bl));
                    o2y[j] = pk2(e1, e2);
                    Sa += e1; Sb += e2;
                }
                float ha  = 0.5f * rcpf(Sa);
                float hb2 = 0.5f * rcpf(Sb);
                float klq = 0.f;
                #pragma unroll
                for (int j = 0; j < D16; ++j) {
                    float e1, e2;
                    upk2(o2y[j], e1, e2);
                    float q = fmaxf(fmaf(e1, ha, e2 * hb2), EPSQ);
                    klq = fmaf(p_sm[j], lg2a(q), klq);
                }
                if (has2) locmin = fminf(locmin, Cc - klq);
            }
        }
    }

    // ---- block min-reduce ----
    #pragma unroll
    for (int off = 16; off; off >>= 1)
        locmin = fminf(locmin, __shfl_xor_sync(0xffffffffu, locmin, off));
    if ((tid & 31) == 0) wmin_sm[tid >> 5] = locmin;
    __syncthreads();

    // ---- last-block-done global reduce (single kernel, replay-safe) ----
    if (tid == 0) {
        float v = fminf(wmin_sm[0], wmin_sm[1]);
        g_part[pair * BLK_PER_PAIR + cblk] = v;
        __threadfence();
        unsigned r = atomicAdd(&g_cnt[pair], 1u);
        last_sm = (r == BLK_PER_PAIR - 1);
    }
    __syncthreads();
    if (last_sm) {
        if (tid < 32) {
            __threadfence();
            const volatile float* vp = g_part + pair * BLK_PER_PAIR;
            float v = vp[tid];
            #pragma unroll
            for (int off = 16; off; off >>= 1)
                v = fminf(v, __shfl_xor_sync(0xffffffffu, v, off));
            if (tid == 0) {
                out[pair] = v;          // out layout: [dir*8 + b] == pair
                g_cnt[pair] = 0;        // reset for next replay (deterministic)
            }
        }
    }
}

extern "C" void kernel_launch(void* const* d_in, const int* in_sizes, int n_in,
                              void* d_out, int out_size) {
    const float* state = (const float*)d_in[0];
    const float* cw1 = (const float*)d_in[1];
    const float* cb1 = (const float*)d_in[2];
    const float* cw2 = (const float*)d_in[3];
    const float* cb2 = (const float*)d_in[4];
    const float* ew1 = (const float*)d_in[5];
    const float* eb1 = (const float*)d_in[6];
    const float* ew2 = (const float*)d_in[7];
    const float* eb2 = (const float*)d_in[8];
    float* out = (float*)d_out;

    phi_kernel<<<NPAIR * BLK_PER_PAIR, TPB>>>(state, cw1, cb1, cw2, cb2,
                                              ew1, eb1, ew2, eb2, out);
}

// round 8
// speedup vs baseline: 1.6052x; 1.0283x over previous
#include <cuda_runtime.h>

#define D16 16
#define H64 64
#define NMASK 32767
#define EPSQ 1e-10f
#define L2E 1.4426950408889634f

#define TPB 64
#define IPT 10            // masks per thread (5 Gray-adjacent pairs)
#define BLK_PER_PAIR 52   // 52 blocks * 64 threads * 10 masks = 33280 >= 32767; grid 832 = single wave
#define NPAIR 16

__device__ float    g_part[NPAIR * 64];
__device__ unsigned g_cnt[NPAIR];   // zero-initialized; reset by last block each run

static __device__ __forceinline__ unsigned long long pk2(float lo, float hi) {
    unsigned long long r;
    asm("mov.b64 %0, {%1, %2};" : "=l"(r) : "f"(lo), "f"(hi));
    return r;
}
static __device__ __forceinline__ void upk2(unsigned long long v, float& lo, float& hi) {
    asm("mov.b64 {%0, %1}, %2;" : "=f"(lo), "=f"(hi) : "l"(v));
}
static __device__ __forceinline__ unsigned long long ffma2(unsigned long long a,
                                                           unsigned long long b,
                                                           unsigned long long c) {
    unsigned long long d;
    asm("fma.rn.f32x2 %0, %1, %2, %3;" : "=l"(d) : "l"(a), "l"(b), "l"(c));
    return d;
}
static __device__ __forceinline__ float ex2f(float x) {
    float y; asm("ex2.approx.f32 %0, %1;" : "=f"(y) : "f"(x)); return y;
}
static __device__ __forceinline__ float lg2a(float x) {
    float y; asm("lg2.approx.f32 %0, %1;" : "=f"(y) : "f"(x)); return y;
}
static __device__ __forceinline__ float rcpf(float x) {
    float y; asm("rcp.approx.f32 %0, %1;" : "=f"(y) : "f"(x)); return y;
}

__global__ void __launch_bounds__(TPB, 6)
phi_kernel(const float* __restrict__ state,
           const float* __restrict__ cw1, const float* __restrict__ cb1,
           const float* __restrict__ cw2, const float* __restrict__ cb2,
           const float* __restrict__ ew1, const float* __restrict__ eb1,
           const float* __restrict__ ew2, const float* __restrict__ eb2,
           float* __restrict__ out) {
    __shared__ float acc_sm[H64 * TPB];              // per-thread Gray accumulator (16 KB)
    __shared__ float cT_sm[D16 * H64];               // [d][h] = W1[h,d]*state[b,d] (4 KB)
    __shared__ unsigned long long w2p_sm[H64 * D16]; // [h][j] = pack(W2[j,h], W2[j,h]) (8 KB)
    __shared__ float T_sm[H64];                      // 2*b1 + sum_d c[h][d]
    __shared__ float b1_sm[H64];
    __shared__ float b2L_sm[D16];                    // b2[j] * log2(e)
    __shared__ float p_sm[D16];
    __shared__ float C_sm;
    __shared__ float hfull_sm[H64];
    __shared__ float wmin_sm[TPB / 32];
    __shared__ int   last_sm;

    const int pair = blockIdx.x / BLK_PER_PAIR;
    const int cblk = blockIdx.x % BLK_PER_PAIR;
    const int b    = pair & 7;
    const int dir  = pair >> 3;
    const float* __restrict__ w1 = dir ? ew1 : cw1;
    const float* __restrict__ b1 = dir ? eb1 : cb1;
    const float* __restrict__ w2 = dir ? ew2 : cw2;
    const float* __restrict__ b2 = dir ? eb2 : cb2;

    const int tid = threadIdx.x;

    // ---- stage shared tables (conflict-free stores) ----
    // cT_sm[d*64 + h]: consecutive idx -> consecutive addresses
    for (int idx = tid; idx < D16 * H64; idx += TPB) {
        int d = idx >> 6, h = idx & 63;
        cT_sm[idx] = w1[h * D16 + d] * state[b * D16 + d];
    }
    // w2p_sm[h*16 + j]: consecutive idx -> consecutive addresses
    for (int idx = tid; idx < H64 * D16; idx += TPB) {
        int h = idx >> 4, j = idx & 15;
        float wv = w2[j * H64 + h];
        w2p_sm[idx] = pk2(wv, wv);
    }
    if (tid < D16) b2L_sm[tid] = b2[tid] * L2E;
    {
        b1_sm[tid] = b1[tid];
        if (tid + TPB < H64) b1_sm[tid + TPB] = b1[tid + TPB];
    }
    __syncthreads();

    {   // T and full hidden (one h per thread, TPB == H64)
        float s = 0.f;
        #pragma unroll
        for (int d = 0; d < D16; ++d) s += cT_sm[d * H64 + tid];
        float t = 2.f * b1_sm[tid] + s;
        T_sm[tid] = t;
        hfull_sm[tid] = fmaxf(t - b1_sm[tid], 0.f);
    }
    __syncthreads();
    // ---- full-state softmax p, C = sum p*log2(p); warp-cooperative ----
    if (tid < 32) {
        float e = 0.f;
        const int j = tid & 15;
        if (tid < D16) {
            float z = b2[j];
            #pragma unroll
            for (int h = 0; h < H64; ++h) z = fmaf(w2[j * H64 + h], hfull_sm[h], z);
            e = ex2f(z * L2E);
        }
        float S = e;
        #pragma unroll
        for (int off = 8; off; off >>= 1) S += __shfl_xor_sync(0xffffffffu, S, off);
        if (tid < D16) {
            float p = fmaxf(e * rcpf(S), EPSQ);
            p_sm[j] = p;
            float cpart = p * lg2a(p);
            #pragma unroll
            for (int off = 8; off; off >>= 1)
                cpart += __shfl_xor_sync(0x0000ffffu, cpart, off);
            if (tid == 0) C_sm = cpart;
        }
    }
    __syncthreads();

    const float Cc = C_sm;
    const int t  = cblk * TPB + tid;
    const int i0 = 1 + t * IPT;   // odd, since IPT is even
    float locmin = __int_as_float(0x7f800000);  // +inf

    if (i0 <= NMASK) {
        const int i1 = min(i0 + IPT, NMASK + 1);
        unsigned m = (unsigned)i0 ^ ((unsigned)i0 >> 1);  // gray(i0)

        // ---- init accumulator in shared: acc = b1 + sum_{d in m} c_d ----
        #pragma unroll
        for (int h = 0; h < H64; ++h) {
            float a = b1_sm[h];
            #pragma unroll
            for (int d = 0; d < D16; ++d) {
                float bd = ((m >> d) & 1u) ? 1.f : 0.f;
                a = fmaf(bd, cT_sm[d * H64 + h], a);
            }
            acc_sm[h * TPB + tid] = a;
        }

        // ---- pair loop: masks (i, i+1), i odd ----
        for (int i = i0; i < i1; i += 2) {
            const bool first = (i == i0);
            const bool has2  = (i + 1 < i1);

            float s1;
            if (first) { s1 = 0.f; }
            else       { m ^= 1u; s1 = (m & 1u) ? 1.f : -1.f; }  // odd i: bit 0 flips

            int dd2 = __ffs(i + 1) - 1;          // transition i -> i+1
            float s2 = 0.f;
            if (has2) {
                m ^= (1u << dd2);
                s2 = ((m >> dd2) & 1u) ? 1.f : -1.f;
            }

            unsigned long long o2x[D16], o2y[D16];
            #pragma unroll
            for (int j = 0; j < D16; ++j) { o2x[j] = 0ull; o2y[j] = 0ull; }

            // ---- fused dual Gray update + two dual second layers (packed f32x2) ----
            #pragma unroll
            for (int hb = 0; hb < H64 / 4; ++hb) {
                const float4 Tv  = reinterpret_cast<const float4*>(T_sm)[hb];
                const float4 Cv0 = reinterpret_cast<const float4*>(&cT_sm[0])[hb];
                const float4 Cv2 = reinterpret_cast<const float4*>(&cT_sm[dd2 * H64])[hb];
                #pragma unroll
                for (int k = 0; k < 4; ++k) {
                    const int h = hb * 4 + k;
                    float cv0 = (k == 0) ? Cv0.x : (k == 1) ? Cv0.y : (k == 2) ? Cv0.z : Cv0.w;
                    float cv2 = (k == 0) ? Cv2.x : (k == 1) ? Cv2.y : (k == 2) ? Cv2.z : Cv2.w;
                    float tt  = (k == 0) ? Tv.x  : (k == 1) ? Tv.y  : (k == 2) ? Tv.z  : Tv.w;
                    float a0 = acc_sm[h * TPB + tid];
                    float a1 = fmaf(s1, cv0, a0);
                    float a2 = fmaf(s2, cv2, a1);
                    acc_sm[h * TPB + tid] = a2;
                    unsigned long long rab1 = pk2(fmaxf(a1, 0.f), fmaxf(tt - a1, 0.f));
                    unsigned long long rab2 = pk2(fmaxf(a2, 0.f), fmaxf(tt - a2, 0.f));
                    const ulonglong2* wrow = reinterpret_cast<const ulonglong2*>(&w2p_sm[h * D16]);
                    #pragma unroll
                    for (int jj = 0; jj < 8; ++jj) {
                        ulonglong2 wv = wrow[jj];
                        o2x[2 * jj]     = ffma2(rab1, wv.x, o2x[2 * jj]);
                        o2x[2 * jj + 1] = ffma2(rab1, wv.y, o2x[2 * jj + 1]);
                        o2y[2 * jj]     = ffma2(rab2, wv.x, o2y[2 * jj]);
                        o2y[2 * jj + 1] = ffma2(rab2, wv.y, o2y[2 * jj + 1]);
                    }
                }
            }

            // ---- dual softmax + KL, mask 1 ----
            {
                float Sa = 0.f, Sb = 0.f;
                #pragma unroll
                for (int j = 0; j < D16; ++j) {
                    float za, zb;
                    upk2(o2x[j], za, zb);
                    float bl = b2L_sm[j];
                    float e1 = ex2f(fmaf(za, L2E, bl));
                    float e2 = ex2f(fmaf(zb, L2E, bl));
                    o2x[j] = pk2(e1, e2);
                    Sa += e1; Sb += e2;
                }
                float ha  = 0.5f * rcpf(Sa);
                float hb2 = 0.5f * rcpf(Sb);
                float klq = 0.f;
                #pragma unroll
                for (int j = 0; j < D16; ++j) {
                    float e1, e2;
                    upk2(o2x[j], e1, e2);
                    float q = fmaxf(fmaf(e1, ha, e2 * hb2), EPSQ);
                    klq = fmaf(p_sm[j], lg2a(q), klq);
                }
                locmin = fminf(locmin, Cc - klq);
            }
            // ---- dual softmax + KL, mask 2 (guarded) ----
            {
                float Sa = 0.f, Sb = 0.f;
                #pragma unroll
                for (int j = 0; j < D16; ++j) {
                    float za, zb;
                    upk2(o2y[j], za, zb);
                    float bl = b2L_sm[j];
                    float e1 = ex2f(fmaf(za, L2E, bl));
                    float e2 = ex2f(fmaf(zb, L2E, bl));
                    o2y[j] = pk2(e1, e2);
                    Sa += e1; Sb += e2;
                }
                float ha  = 0.5f * rcpf(Sa);
                float hb2 = 0.5f * rcpf(Sb);
                float klq = 0.f;
                #pragma unroll
                for (int j = 0; j < D16; ++j) {
                    float e1, e2;
                    upk2(o2y[j], e1, e2);
                    float q = fmaxf(fmaf(e1, ha, e2 * hb2), EPSQ);
                    klq = fmaf(p_sm[j], lg2a(q), klq);
                }
                if (has2) locmin = fminf(locmin, Cc - klq);
            }
        }
    }

    // ---- block min-reduce ----
    #pragma unroll
    for (int off = 16; off; off >>= 1)
        locmin = fminf(locmin, __shfl_xor_sync(0xffffffffu, locmin, off));
    if ((tid & 31) == 0) wmin_sm[tid >> 5] = locmin;
    __syncthreads();

    // ---- last-block-done global reduce (single kernel, replay-safe) ----
    if (tid == 0) {
        float v = fminf(wmin_sm[0], wmin_sm[1]);
        g_part[pair * 64 + cblk] = v;
        __threadfence();
        unsigned r = atomicAdd(&g_cnt[pair], 1u);
        last_sm = (r == BLK_PER_PAIR - 1);
    }
    __syncthreads();
    if (last_sm) {
        if (tid < 32) {
            __threadfence();
            const volatile float* vp = g_part + pair * 64;
            float v = vp[tid];
            if (tid + 32 < BLK_PER_PAIR) v = fminf(v, vp[tid + 32]);
            #pragma unroll
            for (int off = 16; off; off >>= 1)
                v = fminf(v, __shfl_xor_sync(0xffffffffu, v, off));
            if (tid == 0) {
                out[pair] = v;          // out layout: [dir*8 + b] == pair
                g_cnt[pair] = 0;        // reset for next replay (deterministic)
            }
        }
    }
}

extern "C" void kernel_launch(void* const* d_in, const int* in_sizes, int n_in,
                              void* d_out, int out_size) {
    const float* state = (const float*)d_in[0];
    const float* cw1 = (const float*)d_in[1];
    const float* cb1 = (const float*)d_in[2];
    const float* cw2 = (const float*)d_in[3];
    const float* cb2 = (const float*)d_in[4];
    const float* ew1 = (const float*)d_in[5];
    const float* eb1 = (const float*)d_in[6];
    const float* ew2 = (const float*)d_in[7];
    const float* eb2 = (const float*)d_in[8];
    float* out = (float*)d_out;

    phi_kernel<<<NPAIR * BLK_PER_PAIR, TPB>>>(state, cw1, cb1, cw2, cb2,
                                              ew1, eb1, ew2, eb2, out);
}

// round 9
// speedup vs baseline: 1.7746x; 1.1055x over previous
#include <cuda_runtime.h>

#define D16 16
#define H64 64
#define NMASK 32767
#define EPSQ 1e-10f
#define L2E 1.4426950408889634f

#define TPB 64
#define IPT 8             // masks per thread (4 Gray-adjacent pairs)
#define BLK_PER_PAIR 64   // 64 blocks * 64 threads * 8 masks = 32768 >= 32767; grid 1024 <= 7*148
#define NPAIR 16

__device__ float    g_part[NPAIR * 64];
__device__ unsigned g_cnt[NPAIR];   // zero-initialized; reset by last block each run

static __device__ __forceinline__ unsigned long long pk2(float lo, float hi) {
    unsigned long long r;
    asm("mov.b64 %0, {%1, %2};" : "=l"(r) : "f"(lo), "f"(hi));
    return r;
}
static __device__ __forceinline__ void upk2(unsigned long long v, float& lo, float& hi) {
    asm("mov.b64 {%0, %1}, %2;" : "=f"(lo), "=f"(hi) : "l"(v));
}
static __device__ __forceinline__ unsigned long long ffma2(unsigned long long a,
                                                           unsigned long long b,
                                                           unsigned long long c) {
    unsigned long long d;
    asm("fma.rn.f32x2 %0, %1, %2, %3;" : "=l"(d) : "l"(a), "l"(b), "l"(c));
    return d;
}
static __device__ __forceinline__ float ex2f(float x) {
    float y; asm("ex2.approx.f32 %0, %1;" : "=f"(y) : "f"(x)); return y;
}
static __device__ __forceinline__ float lg2a(float x) {
    float y; asm("lg2.approx.f32 %0, %1;" : "=f"(y) : "f"(x)); return y;
}
static __device__ __forceinline__ float rcpf(float x) {
    float y; asm("rcp.approx.f32 %0, %1;" : "=f"(y) : "f"(x)); return y;
}

__global__ void __launch_bounds__(TPB, 7)
phi_kernel(const float* __restrict__ state,
           const float* __restrict__ cw1, const float* __restrict__ cb1,
           const float* __restrict__ cw2, const float* __restrict__ cb2,
           const float* __restrict__ ew1, const float* __restrict__ eb1,
           const float* __restrict__ ew2, const float* __restrict__ eb2,
           float* __restrict__ out) {
    __shared__ float acc_sm[H64 * TPB];              // per-thread Gray accumulator (16 KB)
    __shared__ float cT_sm[D16 * H64];               // [d][h] = W1[h,d]*state[b,d] (4 KB)
    __shared__ unsigned long long w2j_sm[H64 * 8];   // [h][jp] = pack(W2[2jp,h], W2[2jp+1,h]) (4 KB)
    __shared__ float T_sm[H64];                      // 2*b1 + sum_d c[h][d]
    __shared__ float b1_sm[H64];
    __shared__ float b2L_sm[D16];                    // b2[j] * log2(e)
    __shared__ float p_sm[D16];
    __shared__ float C_sm;
    __shared__ float hfull_sm[H64];
    __shared__ float wmin_sm[TPB / 32];
    __shared__ int   last_sm;

    const int pair = blockIdx.x / BLK_PER_PAIR;
    const int cblk = blockIdx.x % BLK_PER_PAIR;
    const int b    = pair & 7;
    const int dir  = pair >> 3;
    const float* __restrict__ w1 = dir ? ew1 : cw1;
    const float* __restrict__ b1 = dir ? eb1 : cb1;
    const float* __restrict__ w2 = dir ? ew2 : cw2;
    const float* __restrict__ b2 = dir ? eb2 : cb2;

    const int tid = threadIdx.x;

    // ---- stage shared tables (conflict-free stores) ----
    for (int idx = tid; idx < D16 * H64; idx += TPB) {
        int d = idx >> 6, h = idx & 63;
        cT_sm[idx] = w1[h * D16 + d] * state[b * D16 + d];
    }
    // w2j_sm[h*8 + jp] = pack(W2[2jp, h], W2[2jp+1, h])
    for (int idx = tid; idx < H64 * 8; idx += TPB) {
        int h = idx >> 3, jp = idx & 7;
        w2j_sm[idx] = pk2(w2[(2 * jp) * H64 + h], w2[(2 * jp + 1) * H64 + h]);
    }
    if (tid < D16) b2L_sm[tid] = b2[tid] * L2E;
    {
        b1_sm[tid] = b1[tid];
        if (tid + TPB < H64) b1_sm[tid + TPB] = b1[tid + TPB];
    }
    __syncthreads();

    {   // T and full hidden (one h per thread, TPB == H64)
        float s = 0.f;
        #pragma unroll
        for (int d = 0; d < D16; ++d) s += cT_sm[d * H64 + tid];
        float t = 2.f * b1_sm[tid] + s;
        T_sm[tid] = t;
        hfull_sm[tid] = fmaxf(t - b1_sm[tid], 0.f);
    }
    __syncthreads();
    // ---- full-state softmax p, C = sum p*log2(p); warp-cooperative ----
    if (tid < 32) {
        float e = 0.f;
        const int j = tid & 15;
        if (tid < D16) {
            float z = b2[j];
            #pragma unroll
            for (int h = 0; h < H64; ++h) z = fmaf(w2[j * H64 + h], hfull_sm[h], z);
            e = ex2f(z * L2E);
        }
        float S = e;
        #pragma unroll
        for (int off = 8; off; off >>= 1) S += __shfl_xor_sync(0xffffffffu, S, off);
        if (tid < D16) {
            float p = fmaxf(e * rcpf(S), EPSQ);
            p_sm[j] = p;
            float cpart = p * lg2a(p);
            #pragma unroll
            for (int off = 8; off; off >>= 1)
                cpart += __shfl_xor_sync(0x0000ffffu, cpart, off);
            if (tid == 0) C_sm = cpart;
        }
    }
    __syncthreads();

    const float Cc = C_sm;
    const int t  = cblk * TPB + tid;
    const int i0 = 1 + t * IPT;   // odd, since IPT is even
    float locmin = __int_as_float(0x7f800000);  // +inf

    if (i0 <= NMASK) {
        const int i1 = min(i0 + IPT, NMASK + 1);
        unsigned m = (unsigned)i0 ^ ((unsigned)i0 >> 1);  // gray(i0)

        // ---- init accumulator in shared: acc = b1 + sum_{d in m} c_d ----
        #pragma unroll
        for (int h = 0; h < H64; ++h) {
            float a = b1_sm[h];
            #pragma unroll
            for (int d = 0; d < D16; ++d) {
                float bd = ((m >> d) & 1u) ? 1.f : 0.f;
                a = fmaf(bd, cT_sm[d * H64 + h], a);
            }
            acc_sm[h * TPB + tid] = a;
        }

        // ---- pair loop: masks (i, i+1), i odd ----
        for (int i = i0; i < i1; i += 2) {
            const bool first = (i == i0);
            const bool has2  = (i + 1 < i1);

            float s1;
            if (first) { s1 = 0.f; }
            else       { m ^= 1u; s1 = (m & 1u) ? 1.f : -1.f; }  // odd i: bit 0 flips

            int dd2 = __ffs(i + 1) - 1;          // transition i -> i+1
            float s2 = 0.f;
            if (has2) {
                m ^= (1u << dd2);
                s2 = ((m >> dd2) & 1u) ? 1.f : -1.f;
            }

            // per-mask logits, j-pair packed: oA = repertoire a, oB = repertoire b
            unsigned long long oA1[8], oB1[8], oA2[8], oB2[8];
            #pragma unroll
            for (int jp = 0; jp < 8; ++jp) { oA1[jp] = 0ull; oB1[jp] = 0ull; oA2[jp] = 0ull; oB2[jp] = 0ull; }

            // ---- fused dual Gray update + two dual second layers (f32x2 over j-pairs) ----
            #pragma unroll
            for (int hb = 0; hb < H64 / 4; ++hb) {
                const float4 Tv  = reinterpret_cast<const float4*>(T_sm)[hb];
                const float4 Cv0 = reinterpret_cast<const float4*>(&cT_sm[0])[hb];
                const float4 Cv2 = reinterpret_cast<const float4*>(&cT_sm[dd2 * H64])[hb];
                #pragma unroll
                for (int k = 0; k < 4; ++k) {
                    const int h = hb * 4 + k;
                    float cv0 = (k == 0) ? Cv0.x : (k == 1) ? Cv0.y : (k == 2) ? Cv0.z : Cv0.w;
                    float cv2 = (k == 0) ? Cv2.x : (k == 1) ? Cv2.y : (k == 2) ? Cv2.z : Cv2.w;
                    float tt  = (k == 0) ? Tv.x  : (k == 1) ? Tv.y  : (k == 2) ? Tv.z  : Tv.w;
                    float a0 = acc_sm[h * TPB + tid];
                    float a1 = fmaf(s1, cv0, a0);
                    float a2 = fmaf(s2, cv2, a1);
                    acc_sm[h * TPB + tid] = a2;
                    unsigned long long rA1 = pk2(fmaxf(a1, 0.f), fmaxf(a1, 0.f));
                    unsigned long long rB1 = pk2(fmaxf(tt - a1, 0.f), fmaxf(tt - a1, 0.f));
                    unsigned long long rA2 = pk2(fmaxf(a2, 0.f), fmaxf(a2, 0.f));
                    unsigned long long rB2 = pk2(fmaxf(tt - a2, 0.f), fmaxf(tt - a2, 0.f));
                    const ulonglong2* wrow = reinterpret_cast<const ulonglong2*>(&w2j_sm[h * 8]);
                    #pragma unroll
                    for (int jj = 0; jj < 4; ++jj) {
                        ulonglong2 wv = wrow[jj];
                        oA1[2 * jj]     = ffma2(rA1, wv.x, oA1[2 * jj]);
                        oA1[2 * jj + 1] = ffma2(rA1, wv.y, oA1[2 * jj + 1]);
                        oB1[2 * jj]     = ffma2(rB1, wv.x, oB1[2 * jj]);
                        oB1[2 * jj + 1] = ffma2(rB1, wv.y, oB1[2 * jj + 1]);
                        oA2[2 * jj]     = ffma2(rA2, wv.x, oA2[2 * jj]);
                        oA2[2 * jj + 1] = ffma2(rA2, wv.y, oA2[2 * jj + 1]);
                        oB2[2 * jj]     = ffma2(rB2, wv.x, oB2[2 * jj]);
                        oB2[2 * jj + 1] = ffma2(rB2, wv.y, oB2[2 * jj + 1]);
                    }
                }
            }

            // ---- dual softmax + KL, mask 1 ----
            {
                float Sa = 0.f, Sb = 0.f;
                #pragma unroll
                for (int jp = 0; jp < 8; ++jp) {
                    float za0, za1, zb0, zb1;
                    upk2(oA1[jp], za0, za1);
                    upk2(oB1[jp], zb0, zb1);
                    float bl0 = b2L_sm[2 * jp], bl1 = b2L_sm[2 * jp + 1];
                    float ea0 = ex2f(fmaf(za0, L2E, bl0));
                    float ea1 = ex2f(fmaf(za1, L2E, bl1));
                    float eb0 = ex2f(fmaf(zb0, L2E, bl0));
                    float eb1 = ex2f(fmaf(zb1, L2E, bl1));
                    oA1[jp] = pk2(ea0, ea1);
                    oB1[jp] = pk2(eb0, eb1);
                    Sa += ea0 + ea1; Sb += eb0 + eb1;
                }
                float ha = 0.5f * rcpf(Sa);
                float hb = 0.5f * rcpf(Sb);
                float klq = 0.f;
                #pragma unroll
                for (int jp = 0; jp < 8; ++jp) {
                    float ea0, ea1, eb0, eb1;
                    upk2(oA1[jp], ea0, ea1);
                    upk2(oB1[jp], eb0, eb1);
                    float q0 = fmaxf(fmaf(ea0, ha, eb0 * hb), EPSQ);
                    float q1 = fmaxf(fmaf(ea1, ha, eb1 * hb), EPSQ);
                    klq = fmaf(p_sm[2 * jp], lg2a(q0), klq);
                    klq = fmaf(p_sm[2 * jp + 1], lg2a(q1), klq);
                }
                locmin = fminf(locmin, Cc - klq);
            }
            // ---- dual softmax + KL, mask 2 (guarded) ----
            {
                float Sa = 0.f, Sb = 0.f;
                #pragma unroll
                for (int jp = 0; jp < 8; ++jp) {
                    float za0, za1, zb0, zb1;
                    upk2(oA2[jp], za0, za1);
                    upk2(oB2[jp], zb0, zb1);
                    float bl0 = b2L_sm[2 * jp], bl1 = b2L_sm[2 * jp + 1];
                    float ea0 = ex2f(fmaf(za0, L2E, bl0));
                    float ea1 = ex2f(fmaf(za1, L2E, bl1));
                    float eb0 = ex2f(fmaf(zb0, L2E, bl0));
                    float eb1 = ex2f(fmaf(zb1, L2E, bl1));
                    oA2[jp] = pk2(ea0, ea1);
                    oB2[jp] = pk2(eb0, eb1);
                    Sa += ea0 + ea1; Sb += eb0 + eb1;
                }
                float ha = 0.5f * rcpf(Sa);
                float hb = 0.5f * rcpf(Sb);
                float klq = 0.f;
                #pragma unroll
                for (int jp = 0; jp < 8; ++jp) {
                    float ea0, ea1, eb0, eb1;
                    upk2(oA2[jp], ea0, ea1);
                    upk2(oB2[jp], eb0, eb1);
                    float q0 = fmaxf(fmaf(ea0, ha, eb0 * hb), EPSQ);
                    float q1 = fmaxf(fmaf(ea1, ha, eb1 * hb), EPSQ);
                    klq = fmaf(p_sm[2 * jp], lg2a(q0), klq);
                    klq = fmaf(p_sm[2 * jp + 1], lg2a(q1), klq);
                }
                if (has2) locmin = fminf(locmin, Cc - klq);
            }
        }
    }

    // ---- block min-reduce ----
    #pragma unroll
    for (int off = 16; off; off >>= 1)
        locmin = fminf(locmin, __shfl_xor_sync(0xffffffffu, locmin, off));
    if ((tid & 31) == 0) wmin_sm[tid >> 5] = locmin;
    __syncthreads();

    // ---- last-block-done global reduce (single kernel, replay-safe) ----
    if (tid == 0) {
        float v = fminf(wmin_sm[0], wmin_sm[1]);
        g_part[pair * 64 + cblk] = v;
        __threadfence();
        unsigned r = atomicAdd(&g_cnt[pair], 1u);
        last_sm = (r == BLK_PER_PAIR - 1);
    }
    __syncthreads();
    if (last_sm) {
        if (tid < 32) {
            __threadfence();
            const volatile float* vp = g_part + pair * 64;
            float v = fminf(vp[tid], vp[tid + 32]);
            #pragma unroll
            for (int off = 16; off; off >>= 1)
                v = fminf(v, __shfl_xor_sync(0xffffffffu, v, off));
            if (tid == 0) {
                out[pair] = v;          // out layout: [dir*8 + b] == pair
                g_cnt[pair] = 0;        // reset for next replay (deterministic)
            }
        }
    }
}

extern "C" void kernel_launch(void* const* d_in, const int* in_sizes, int n_in,
                              void* d_out, int out_size) {
    const float* state = (const float*)d_in[0];
    const float* cw1 = (const float*)d_in[1];
    const float* cb1 = (const float*)d_in[2];
    const float* cw2 = (const float*)d_in[3];
    const float* cb2 = (const float*)d_in[4];
    const float* ew1 = (const float*)d_in[5];
    const float* eb1 = (const float*)d_in[6];
    const float* ew2 = (const float*)d_in[7];
    const float* eb2 = (const float*)d_in[8];
    float* out = (float*)d_out;

    phi_kernel<<<NPAIR * BLK_PER_PAIR, TPB>>>(state, cw1, cb1, cw2, cb2,
                                              ew1, eb1, ew2, eb2, out);
}